// round 4
// baseline (speedup 1.0000x reference)
#include <cuda_runtime.h>

// StreamNet_K3_S1: fused halo-concat + 3x3 VALID conv + bias.
// x:[8,32,256,256] rbuf:[8,32,256,2] bbuf:[8,32,2,258] W:[32,32,3,3] bias:[32]
// out:[8,32,256,256]
//
// padded[(P+2)x(P+2)] view:
//   pr<2           -> bbuf[b,ci,pr,pc]
//   pr>=2, pc<2    -> rbuf[b,ci,pr-2,pc]
//   pr>=2, pc>=2   -> (pc-2==P-1) ? 0 : x[b,ci,pr-2,pc-2]
// out[b,co,i,j] = bias[co] + sum_{ci,kh,kw} padded[b,ci,i+kh,j+kw]*W[co,ci,kh,kw]

#define BATCH 8
#define CH 32
#define P 256
#define PP (P + 2)

#define TH 8              // output rows per block
#define TW 32             // output cols per block
#define IN_H (TH + 2)     // 10 padded rows in tile
#define IN_W (TW + 2)     // 34 padded cols in tile
#define IN_WP 36          // smem row stride (floats), keeps 16B alignment
#define W_STRIDE 289      // 32*9 + 1 pad -> co-delta maps to distinct banks

#define SMEM_IN_FLOATS (CH * IN_H * IN_WP)   // 11520
#define SMEM_W_FLOATS  (CH * W_STRIDE)       // 9248
#define SMEM_BYTES ((SMEM_IN_FLOATS + SMEM_W_FLOATS) * 4)  // 83072 B

__global__ __launch_bounds__(256, 2)
void streamnet_conv3x3_kernel(const float* __restrict__ x,
                              const float* __restrict__ rbuf,
                              const float* __restrict__ bbuf,
                              const float* __restrict__ Wt,
                              const float* __restrict__ bias,
                              float* __restrict__ out)
{
    extern __shared__ float smem[];
    float* sIn = smem;                       // [CH][IN_H][IN_WP]
    float* sW  = smem + SMEM_IN_FLOATS;      // [CH][W_STRIDE]

    const int tid   = threadIdx.x;
    const int b     = blockIdx.z;
    const int r0    = blockIdx.y * TH;       // output row base
    const int c0blk = blockIdx.x * TW;       // output col base

    // ---- load all weights into smem (9216 elems), padded stride ----
    #pragma unroll 4
    for (int i = tid; i < CH * CH * 9; i += 256) {
        int co   = i / 288;
        int rest = i - co * 288;             // ci*9 + k
        sW[co * W_STRIDE + rest] = Wt[i];
    }

    // ---- load padded input tile: 32ci x 10 x 34, halo-mapped ----
    for (int t = tid; t < CH * IN_H * IN_W; t += 256) {
        int ci   = t / (IN_H * IN_W);
        int rem  = t - ci * (IN_H * IN_W);
        int y    = rem / IN_W;
        int xcol = rem - y * IN_W;
        int pr   = r0 + y;                   // padded row  [0, 258)
        int pc   = c0blk + xcol;             // padded col  [0, 258)
        float v;
        if (pr < 2) {
            v = bbuf[((b * CH + ci) * 2 + pr) * PP + pc];
        } else {
            int xr = pr - 2;
            if (pc < 2) {
                v = rbuf[((b * CH + ci) * P + xr) * 2 + pc];
            } else {
                int xc = pc - 2;
                v = (xc == P - 1) ? 0.0f
                                  : x[((size_t)(b * CH + ci) * P + xr) * P + xc];
            }
        }
        sIn[ci * (IN_H * IN_WP) + y * IN_WP + xcol] = v;
    }
    __syncthreads();

    // ---- compute: each thread = 1 c_out, 8 rows x 4 cols ----
    const int co = tid >> 3;
    const int c0 = (tid & 7) * 4;            // col offset within tile (also padded-col base)

    float acc[TH][4];
    const float bv = bias[co];
    #pragma unroll
    for (int r = 0; r < TH; r++)
        #pragma unroll
        for (int c = 0; c < 4; c++)
            acc[r][c] = bv;

    const float* wbase = sW + co * W_STRIDE;

    #pragma unroll 1
    for (int ci = 0; ci < CH; ci++) {
        const float* ib = sIn + ci * (IN_H * IN_WP) + c0;

        float w[9];
        #pragma unroll
        for (int k = 0; k < 9; k++) w[k] = wbase[ci * 9 + k];

        // sliding 3-row x 6-col register window (16B-aligned -> LDS.128+LDS.64)
        float win[3][6];
        #pragma unroll
        for (int j = 0; j < 6; j++) {
            win[0][j] = ib[j];
            win[1][j] = ib[IN_WP + j];
        }

        #pragma unroll
        for (int r = 0; r < TH; r++) {
            const float* rowp = ib + (r + 2) * IN_WP;
            #pragma unroll
            for (int j = 0; j < 6; j++) win[(r + 2) % 3][j] = rowp[j];

            #pragma unroll
            for (int kh = 0; kh < 3; kh++) {
                const int wr = (r + kh) % 3;
                #pragma unroll
                for (int kw = 0; kw < 3; kw++) {
                    const float wv = w[kh * 3 + kw];
                    #pragma unroll
                    for (int c = 0; c < 4; c++)
                        acc[r][c] = fmaf(win[wr][c + kw], wv, acc[r][c]);
                }
            }
        }
    }

    // ---- store: float4 per row, contiguous 128B per 8-thread group ----
    #pragma unroll
    for (int r = 0; r < TH; r++) {
        float4 v = make_float4(acc[r][0], acc[r][1], acc[r][2], acc[r][3]);
        float* op = out + ((size_t)(b * CH + co) * P + (r0 + r)) * P + (c0blk + c0);
        *reinterpret_cast<float4*>(op) = v;
    }
}

extern "C" void kernel_launch(void* const* d_in, const int* in_sizes, int n_in,
                              void* d_out, int out_size)
{
    (void)in_sizes; (void)n_in; (void)out_size;
    const float* x    = (const float*)d_in[0];
    const float* rbuf = (const float*)d_in[1];
    const float* bbuf = (const float*)d_in[2];
    const float* Wt   = (const float*)d_in[3];
    const float* bias = (const float*)d_in[4];
    float* out = (float*)d_out;

    static bool inited = false;
    if (!inited) {
        cudaFuncSetAttribute(streamnet_conv3x3_kernel,
                             cudaFuncAttributeMaxDynamicSharedMemorySize, SMEM_BYTES);
        inited = true;
    }

    dim3 grid(P / TW, P / TH, BATCH);   // 8 x 32 x 8 = 2048 blocks
    streamnet_conv3x3_kernel<<<grid, 256, SMEM_BYTES>>>(x, rbuf, bbuf, Wt, bias, out);
}

// round 7
// speedup vs baseline: 1.0140x; 1.0140x over previous
#include <cuda_runtime.h>

// StreamNet_K3_S1: fused halo-concat + 3x3 VALID conv + bias.
// x:[8,32,256,256] rbuf:[8,32,256,2] bbuf:[8,32,2,258] W:[32,32,3,3] bias:[32]
// out:[8,32,256,256]
//
// padded[(P+2)x(P+2)] view:
//   pr<2           -> bbuf[b,ci,pr,pc]
//   pr>=2, pc<2    -> rbuf[b,ci,pr-2,pc]
//   pr>=2, pc>=2   -> (pc-2==P-1) ? 0 : x[b,ci,pr-2,pc-2]
// out[b,co,i,j] = bias[co] + sum_{ci,kh,kw} padded[b,ci,i+kh,j+kw]*W[co,ci,kh,kw]

#define BATCH 8
#define CH 32
#define P 256
#define PP (P + 2)

#define TH 8              // output rows per block
#define TW 32             // output cols per block
#define IN_H (TH + 2)     // 10 padded rows in tile
#define IN_W (TW + 2)     // 34 padded cols in tile
#define IN_WP 36          // smem row stride (floats), keeps 16B alignment
#define W_STRIDE 289      // 32*9 + 1 pad -> co-delta maps to distinct banks

#define SMEM_IN_FLOATS (CH * IN_H * IN_WP)   // 11520
#define SMEM_W_FLOATS  (CH * W_STRIDE)       // 9248
#define SMEM_BYTES ((SMEM_IN_FLOATS + SMEM_W_FLOATS) * 4)  // 83072 B

__global__ __launch_bounds__(256, 2)
void streamnet_conv3x3_kernel(const float* __restrict__ x,
                              const float* __restrict__ rbuf,
                              const float* __restrict__ bbuf,
                              const float* __restrict__ Wt,
                              const float* __restrict__ bias,
                              float* __restrict__ out)
{
    extern __shared__ float smem[];
    float* sIn = smem;                       // [CH][IN_H][IN_WP]
    float* sW  = smem + SMEM_IN_FLOATS;      // [CH][W_STRIDE]

    const int tid   = threadIdx.x;
    const int b     = blockIdx.z;
    const int r0    = blockIdx.y * TH;       // output row base
    const int c0blk = blockIdx.x * TW;       // output col base

    // ---- load all weights into smem (9216 elems), padded stride ----
    #pragma unroll 4
    for (int i = tid; i < CH * CH * 9; i += 256) {
        int co   = i / 288;
        int rest = i - co * 288;             // ci*9 + k
        sW[co * W_STRIDE + rest] = Wt[i];
    }

    // ---- load padded input tile: 32ci x 10 x 34, halo-mapped ----
    for (int t = tid; t < CH * IN_H * IN_W; t += 256) {
        int ci   = t / (IN_H * IN_W);
        int rem  = t - ci * (IN_H * IN_W);
        int y    = rem / IN_W;
        int xcol = rem - y * IN_W;
        int pr   = r0 + y;                   // padded row  [0, 258)
        int pc   = c0blk + xcol;             // padded col  [0, 258)
        float v;
        if (pr < 2) {
            v = bbuf[((b * CH + ci) * 2 + pr) * PP + pc];
        } else {
            int xr = pr - 2;
            if (pc < 2) {
                v = rbuf[((b * CH + ci) * P + xr) * 2 + pc];
            } else {
                int xc = pc - 2;
                v = (xc == P - 1) ? 0.0f
                                  : x[((size_t)(b * CH + ci) * P + xr) * P + xc];
            }
        }
        sIn[ci * (IN_H * IN_WP) + y * IN_WP + xcol] = v;
    }
    __syncthreads();

    // ---- compute: each thread = 1 c_out, 8 rows x 4 cols ----
    const int co = tid >> 3;
    const int c0 = (tid & 7) * 4;            // col offset within tile (also padded-col base)

    float acc[TH][4];
    const float bv = bias[co];
    #pragma unroll
    for (int r = 0; r < TH; r++)
        #pragma unroll
        for (int c = 0; c < 4; c++)
            acc[r][c] = bv;

    const float* wbase = sW + co * W_STRIDE;

    #pragma unroll 1
    for (int ci = 0; ci < CH; ci++) {
        const float* ib = sIn + ci * (IN_H * IN_WP) + c0;

        float w[9];
        #pragma unroll
        for (int k = 0; k < 9; k++) w[k] = wbase[ci * 9 + k];

        // sliding 3-row x 6-col register window (16B-aligned -> LDS.128+LDS.64)
        float win[3][6];
        #pragma unroll
        for (int j = 0; j < 6; j++) {
            win[0][j] = ib[j];
            win[1][j] = ib[IN_WP + j];
        }

        #pragma unroll
        for (int r = 0; r < TH; r++) {
            const float* rowp = ib + (r + 2) * IN_WP;
            #pragma unroll
            for (int j = 0; j < 6; j++) win[(r + 2) % 3][j] = rowp[j];

            #pragma unroll
            for (int kh = 0; kh < 3; kh++) {
                const int wr = (r + kh) % 3;
                #pragma unroll
                for (int kw = 0; kw < 3; kw++) {
                    const float wv = w[kh * 3 + kw];
                    #pragma unroll
                    for (int c = 0; c < 4; c++)
                        acc[r][c] = fmaf(win[wr][c + kw], wv, acc[r][c]);
                }
            }
        }
    }

    // ---- store: float4 per row, contiguous 128B per 8-thread group ----
    #pragma unroll
    for (int r = 0; r < TH; r++) {
        float4 v = make_float4(acc[r][0], acc[r][1], acc[r][2], acc[r][3]);
        float* op = out + ((size_t)(b * CH + co) * P + (r0 + r)) * P + (c0blk + c0);
        *reinterpret_cast<float4*>(op) = v;
    }
}

extern "C" void kernel_launch(void* const* d_in, const int* in_sizes, int n_in,
                              void* d_out, int out_size)
{
    (void)in_sizes; (void)n_in; (void)out_size;
    const float* x    = (const float*)d_in[0];
    const float* rbuf = (const float*)d_in[1];
    const float* bbuf = (const float*)d_in[2];
    const float* Wt   = (const float*)d_in[3];
    const float* bias = (const float*)d_in[4];
    float* out = (float*)d_out;

    static bool inited = false;
    if (!inited) {
        cudaFuncSetAttribute(streamnet_conv3x3_kernel,
                             cudaFuncAttributeMaxDynamicSharedMemorySize, SMEM_BYTES);
        inited = true;
    }

    dim3 grid(P / TW, P / TH, BATCH);   // 8 x 32 x 8 = 2048 blocks
    streamnet_conv3x3_kernel<<<grid, 256, SMEM_BYTES>>>(x, rbuf, bbuf, Wt, bias, out);
}